// round 1
// baseline (speedup 1.0000x reference)
#include <cuda_runtime.h>
#include <math.h>

#define BB 4
#define NSEQ 2048
#define CDIM 768
#define HH 12
#define DD 64
#define HIDD 3072
#define MROWS (BB * NSEQ)   // 8192

// ---------------- scratch (device globals; no allocation allowed) ----------------
__device__ float g_h[MROWS * CDIM];     // LN output (reused for LN1 and LN2)
__device__ float g_q[MROWS * CDIM];     // [B,H,N,D]
__device__ float g_k[MROWS * CDIM];     // [B,H,N,D]
__device__ float g_v[MROWS * CDIM];     // [B,H,N,D]
__device__ float g_o[MROWS * CDIM];     // attention output, [B,N,C]
__device__ float g_x1[MROWS * CDIM];    // after first residual
__device__ float g_hid[MROWS * HIDD];   // FC1 output

// ---------------- LayerNorm: one block per row ----------------
__global__ __launch_bounds__(256) void ln_kernel(const float* __restrict__ X,
                                                 const float* __restrict__ gam,
                                                 const float* __restrict__ bet,
                                                 float* __restrict__ out) {
    int row = blockIdx.x;
    const float* xr = X + (size_t)row * CDIM;
    float v[3];
    float s = 0.f, s2 = 0.f;
#pragma unroll
    for (int i = 0; i < 3; i++) {
        v[i] = xr[threadIdx.x + i * 256];
        s += v[i];
        s2 += v[i] * v[i];
    }
#pragma unroll
    for (int o = 16; o > 0; o >>= 1) {
        s  += __shfl_xor_sync(0xffffffffu, s, o);
        s2 += __shfl_xor_sync(0xffffffffu, s2, o);
    }
    __shared__ float ws[8], ws2[8];
    int wid = threadIdx.x >> 5, lane = threadIdx.x & 31;
    if (lane == 0) { ws[wid] = s; ws2[wid] = s2; }
    __syncthreads();
    if (wid == 0) {
        s  = (lane < 8) ? ws[lane] : 0.f;
        s2 = (lane < 8) ? ws2[lane] : 0.f;
#pragma unroll
        for (int o = 4; o > 0; o >>= 1) {
            s  += __shfl_xor_sync(0xffffffffu, s, o);
            s2 += __shfl_xor_sync(0xffffffffu, s2, o);
        }
        if (lane == 0) { ws[0] = s; ws2[0] = s2; }
    }
    __syncthreads();
    float mu   = ws[0] * (1.0f / CDIM);
    float var  = ws2[0] * (1.0f / CDIM) - mu * mu;
    float rstd = rsqrtf(var + 1e-5f);
#pragma unroll
    for (int i = 0; i < 3; i++) {
        int c = threadIdx.x + i * 256;
        out[(size_t)row * CDIM + c] = (v[i] - mu) * rstd * gam[c] + bet[c];
    }
}

// ---------------- SGEMM: C[M,Nn] = A[M,K] * W[Nn,K]^T (+ epilogue) ----------------
// 128x128 block tile, BK=8, 256 threads, 8x8 per thread.
// EPI: 0 = QKV scatter, 1 = bias + residual, 2 = bias + exact GELU
template <int EPI>
__global__ __launch_bounds__(256) void sgemm_kernel(
    const float* __restrict__ A, const float* __restrict__ W,
    const float* __restrict__ bias, const float* __restrict__ res,
    float* __restrict__ C, int M, int Nn, int K,
    float* __restrict__ qout, float* __restrict__ kout, float* __restrict__ vout) {
    __shared__ float As[8][128];
    __shared__ float Bs[8][128];
    int tid = threadIdx.x;
    int tx = tid & 15, ty = tid >> 4;
    int rowBase = blockIdx.y * 128, colBase = blockIdx.x * 128;

    float acc[8][8];
#pragma unroll
    for (int i = 0; i < 8; i++)
#pragma unroll
        for (int j = 0; j < 8; j++) acc[i][j] = 0.f;

    int lr = tid >> 1;        // 0..127
    int lc = (tid & 1) * 4;   // 0 or 4
    const float* Aptr = A + (size_t)(rowBase + lr) * K + lc;
    const float* Wptr = W + (size_t)(colBase + lr) * K + lc;

    for (int k0 = 0; k0 < K; k0 += 8) {
        float4 a = *(const float4*)(Aptr + k0);
        float4 w = *(const float4*)(Wptr + k0);
        As[lc + 0][lr] = a.x; As[lc + 1][lr] = a.y; As[lc + 2][lr] = a.z; As[lc + 3][lr] = a.w;
        Bs[lc + 0][lr] = w.x; Bs[lc + 1][lr] = w.y; Bs[lc + 2][lr] = w.z; Bs[lc + 3][lr] = w.w;
        __syncthreads();
#pragma unroll
        for (int kk = 0; kk < 8; kk++) {
            float ar[8], br[8];
#pragma unroll
            for (int i = 0; i < 8; i++) ar[i] = As[kk][ty * 8 + i];
#pragma unroll
            for (int j = 0; j < 8; j++) br[j] = Bs[kk][tx * 8 + j];
#pragma unroll
            for (int i = 0; i < 8; i++)
#pragma unroll
                for (int j = 0; j < 8; j++) acc[i][j] += ar[i] * br[j];
        }
        __syncthreads();
    }

#pragma unroll
    for (int i = 0; i < 8; i++) {
        int row = rowBase + ty * 8 + i;
#pragma unroll
        for (int j = 0; j < 8; j++) {
            int col = colBase + tx * 8 + j;
            float vv = acc[i][j];
            if (EPI == 0) {
                // QKV scatter: col = which*768 + h*64 + d; row = b*2048 + n
                int which = col / CDIM;
                int rem   = col - which * CDIM;
                int h = rem >> 6, d = rem & 63;
                int b = row >> 11, n = row & 2047;
                size_t idx = (((size_t)b * HH + h) * NSEQ + n) * DD + d;
                if (which == 0)      qout[idx] = vv * 0.125f;  // D^-0.5
                else if (which == 1) kout[idx] = vv;
                else                 vout[idx] = vv;
            } else if (EPI == 1) {
                C[(size_t)row * Nn + col] = vv + bias[col] + res[(size_t)row * Nn + col];
            } else {
                float u = vv + bias[col];
                C[(size_t)row * Nn + col] = 0.5f * u * (1.0f + erff(u * 0.70710678118654752440f));
            }
        }
    }
}

// ---------------- Flash attention: one thread per query row ----------------
// grid: (N/128, B*H), block: 128 threads. Q pre-scaled by D^-0.5.
#define AT_BN 32
__global__ __launch_bounds__(128) void attn_kernel(const float* __restrict__ Q,
                                                   const float* __restrict__ K,
                                                   const float* __restrict__ V,
                                                   float* __restrict__ O) {
    __shared__ float Ks[AT_BN * DD];
    __shared__ float Vs[AT_BN * DD];
    int bh = blockIdx.y;
    int b = bh / HH, h = bh - b * HH;
    int row = blockIdx.x * 128 + threadIdx.x;   // query index n

    const float4* qp = (const float4*)(Q + (((size_t)bh * NSEQ) + row) * DD);
    float q[DD];
#pragma unroll
    for (int i = 0; i < 16; i++) {
        float4 t = qp[i];
        q[4 * i + 0] = t.x; q[4 * i + 1] = t.y; q[4 * i + 2] = t.z; q[4 * i + 3] = t.w;
    }

    float acc[DD];
#pragma unroll
    for (int d = 0; d < DD; d++) acc[d] = 0.f;
    float m = -1e30f, l = 0.f;

    const float4* Kb = (const float4*)(K + (size_t)bh * NSEQ * DD);
    const float4* Vb = (const float4*)(V + (size_t)bh * NSEQ * DD);

    for (int t = 0; t < NSEQ / AT_BN; ++t) {
        // load K/V tiles: AT_BN*64 floats each = 512 float4, 128 threads x 4
        const float4* ks4 = Kb + t * (AT_BN * DD / 4);
        const float4* vs4 = Vb + t * (AT_BN * DD / 4);
#pragma unroll
        for (int i = 0; i < AT_BN * DD / 4 / 128; i++) {
            ((float4*)Ks)[threadIdx.x + i * 128] = ks4[threadIdx.x + i * 128];
            ((float4*)Vs)[threadIdx.x + i * 128] = vs4[threadIdx.x + i * 128];
        }
        __syncthreads();

        float s[AT_BN];
        float tm = -1e30f;
#pragma unroll
        for (int j = 0; j < AT_BN; j++) {
            const float4* krow = (const float4*)(Ks + j * DD);
            float s0 = 0.f, s1 = 0.f, s2 = 0.f, s3 = 0.f;
#pragma unroll
            for (int i = 0; i < 16; i++) {
                float4 kk = krow[i];
                s0 += q[4 * i + 0] * kk.x;
                s1 += q[4 * i + 1] * kk.y;
                s2 += q[4 * i + 2] * kk.z;
                s3 += q[4 * i + 3] * kk.w;
            }
            s[j] = (s0 + s1) + (s2 + s3);
            tm = fmaxf(tm, s[j]);
        }
        float mn = fmaxf(m, tm);
        float alpha = __expf(m - mn);
        l *= alpha;
#pragma unroll
        for (int d = 0; d < DD; d++) acc[d] *= alpha;
#pragma unroll
        for (int j = 0; j < AT_BN; j++) {
            float p = __expf(s[j] - mn);
            l += p;
            s[j] = p;
        }
        m = mn;
#pragma unroll
        for (int j = 0; j < AT_BN; j++) {
            float p = s[j];
            const float4* vrow = (const float4*)(Vs + j * DD);
#pragma unroll
            for (int i = 0; i < 16; i++) {
                float4 vv = vrow[i];
                acc[4 * i + 0] += p * vv.x;
                acc[4 * i + 1] += p * vv.y;
                acc[4 * i + 2] += p * vv.z;
                acc[4 * i + 3] += p * vv.w;
            }
        }
        __syncthreads();
    }

    float inv = 1.0f / l;
    float* op = O + (((size_t)b * NSEQ) + row) * CDIM + h * DD;
#pragma unroll
    for (int d = 0; d < DD; d++) op[d] = acc[d] * inv;
}

// ---------------- host ----------------
extern "C" void kernel_launch(void* const* d_in, const int* in_sizes, int n_in,
                              void* d_out, int out_size) {
    const float* x      = (const float*)d_in[0];
    const float* ln1_g  = (const float*)d_in[1];
    const float* ln1_b  = (const float*)d_in[2];
    const float* qkv_w  = (const float*)d_in[3];
    const float* proj_w = (const float*)d_in[4];
    const float* proj_b = (const float*)d_in[5];
    const float* ln2_g  = (const float*)d_in[6];
    const float* ln2_b  = (const float*)d_in[7];
    const float* fc1_w  = (const float*)d_in[8];
    const float* fc1_b  = (const float*)d_in[9];
    const float* fc2_w  = (const float*)d_in[10];
    const float* fc2_b  = (const float*)d_in[11];
    float* out = (float*)d_out;

    float *h, *q, *k, *v, *o, *x1, *hid;
    cudaGetSymbolAddress((void**)&h,   g_h);
    cudaGetSymbolAddress((void**)&q,   g_q);
    cudaGetSymbolAddress((void**)&k,   g_k);
    cudaGetSymbolAddress((void**)&v,   g_v);
    cudaGetSymbolAddress((void**)&o,   g_o);
    cudaGetSymbolAddress((void**)&x1,  g_x1);
    cudaGetSymbolAddress((void**)&hid, g_hid);

    // 1. LN1
    ln_kernel<<<MROWS, 256>>>(x, ln1_g, ln1_b, h);
    // 2. QKV GEMM (scatter into [B,H,N,D] q/k/v, q scaled)
    sgemm_kernel<0><<<dim3(3 * CDIM / 128, MROWS / 128), 256>>>(
        h, qkv_w, nullptr, nullptr, nullptr, MROWS, 3 * CDIM, CDIM, q, k, v);
    // 3. flash attention
    attn_kernel<<<dim3(NSEQ / 128, BB * HH), 128>>>(q, k, v, o);
    // 4. proj + bias + residual(x)
    sgemm_kernel<1><<<dim3(CDIM / 128, MROWS / 128), 256>>>(
        o, proj_w, proj_b, x, x1, MROWS, CDIM, CDIM, nullptr, nullptr, nullptr);
    // 5. LN2
    ln_kernel<<<MROWS, 256>>>(x1, ln2_g, ln2_b, h);
    // 6. FC1 + bias + GELU
    sgemm_kernel<2><<<dim3(HIDD / 128, MROWS / 128), 256>>>(
        h, fc1_w, fc1_b, nullptr, hid, MROWS, HIDD, CDIM, nullptr, nullptr, nullptr);
    // 7. FC2 + bias + residual(x1)
    sgemm_kernel<1><<<dim3(CDIM / 128, MROWS / 128), 256>>>(
        hid, fc2_w, fc2_b, x1, out, MROWS, CDIM, HIDD, nullptr, nullptr, nullptr);
}

// round 3
// speedup vs baseline: 1.5749x; 1.5749x over previous
#include <cuda_runtime.h>
#include <cstdint>
#include <math.h>

#define BB 4
#define NSEQ 2048
#define CDIM 768
#define HH 12
#define DD 64
#define HIDD 3072
#define MROWS (BB * NSEQ)   // 8192

// ---------------- scratch ----------------
__device__ float g_h[MROWS * CDIM];
__device__ float g_q[MROWS * CDIM];
__device__ float g_k[MROWS * CDIM];
__device__ float g_v[MROWS * CDIM];
__device__ float g_o[MROWS * CDIM];
__device__ float g_x1[MROWS * CDIM];
__device__ float g_hid[MROWS * HIDD];

__device__ __forceinline__ float to_tf32(float x) {
    float y;
    asm("cvt.rna.tf32.f32 %0, %1;" : "=f"(y) : "f"(x));
    return y;
}

__device__ __forceinline__ void mma_tf32(float* d, const uint32_t* a, const uint32_t* b) {
    asm volatile(
        "mma.sync.aligned.m16n8k8.row.col.f32.tf32.tf32.f32 "
        "{%0,%1,%2,%3}, {%4,%5,%6,%7}, {%8,%9}, {%0,%1,%2,%3};"
        : "+f"(d[0]), "+f"(d[1]), "+f"(d[2]), "+f"(d[3])
        : "r"(a[0]), "r"(a[1]), "r"(a[2]), "r"(a[3]), "r"(b[0]), "r"(b[1]));
}

// ---------------- tensor-core TF32 GEMM: C[M,Nn] = A[M,K] * W[Nn,K]^T ----------------
// BM=BN=128, BK=16, 256 threads (8 warps 2x4), warp tile 64x32, m16n8k8.
// EPI: 0 = QKV scatter, 1 = bias+residual, 2 = bias+GELU
#define LDAS 20   // smem row stride (floats): conflict-free fragment loads

template <int EPI>
__global__ __launch_bounds__(256) void gemm_mma(
    const float* __restrict__ A, const float* __restrict__ W,
    const float* __restrict__ bias, const float* __restrict__ res,
    float* __restrict__ C, int M, int Nn, int K,
    float* __restrict__ qout, float* __restrict__ kout, float* __restrict__ vout) {
    __shared__ float As[2][128 * LDAS];
    __shared__ float Bs[2][128 * LDAS];
    int tid = threadIdx.x, lane = tid & 31, wid = tid >> 5;
    int warpM = wid & 1, warpN = wid >> 1;          // 2 x 4 warps
    int g = lane >> 2, t = lane & 3;
    int rowBase = blockIdx.y * 128, colBase = blockIdx.x * 128;

    float acc[4][4][4];
#pragma unroll
    for (int i = 0; i < 4; i++)
#pragma unroll
        for (int j = 0; j < 4; j++)
#pragma unroll
            for (int e = 0; e < 4; e++) acc[i][j][e] = 0.f;

    float4 ra[2], rb[2];
    const int m0 = (tid * 2) >> 2, kq0 = (tid * 2) & 3;        // idx = tid*2
    const int m1 = (tid * 2 + 1) >> 2, kq1 = (tid * 2 + 1) & 3;

    int nc = K >> 4;
    // prologue: load + store chunk 0
    {
        const float* Ab = A + (size_t)rowBase * K;
        const float* Wb = W + (size_t)colBase * K;
        ra[0] = *(const float4*)(Ab + (size_t)m0 * K + kq0 * 4);
        ra[1] = *(const float4*)(Ab + (size_t)m1 * K + kq1 * 4);
        rb[0] = *(const float4*)(Wb + (size_t)m0 * K + kq0 * 4);
        rb[1] = *(const float4*)(Wb + (size_t)m1 * K + kq1 * 4);
    }
#pragma unroll
    for (int i = 0; i < 2; i++) {
        int m = i ? m1 : m0, kq = i ? kq1 : kq0;
        float4 a = ra[i], b = rb[i];
        a.x = to_tf32(a.x); a.y = to_tf32(a.y); a.z = to_tf32(a.z); a.w = to_tf32(a.w);
        b.x = to_tf32(b.x); b.y = to_tf32(b.y); b.z = to_tf32(b.z); b.w = to_tf32(b.w);
        *(float4*)&As[0][m * LDAS + kq * 4] = a;
        *(float4*)&Bs[0][m * LDAS + kq * 4] = b;
    }
    __syncthreads();

    for (int c = 0; c < nc; c++) {
        int buf = c & 1;
        if (c + 1 < nc) {
            const float* Ab = A + (size_t)rowBase * K + (c + 1) * 16;
            const float* Wb = W + (size_t)colBase * K + (c + 1) * 16;
            ra[0] = *(const float4*)(Ab + (size_t)m0 * K + kq0 * 4);
            ra[1] = *(const float4*)(Ab + (size_t)m1 * K + kq1 * 4);
            rb[0] = *(const float4*)(Wb + (size_t)m0 * K + kq0 * 4);
            rb[1] = *(const float4*)(Wb + (size_t)m1 * K + kq1 * 4);
        }
        // compute on buf
#pragma unroll
        for (int ks = 0; ks < 2; ks++) {
            int k = ks * 8;
            uint32_t af[4][4], bf[4][2];
#pragma unroll
            for (int mt = 0; mt < 4; mt++) {
                int r0 = (warpM * 64 + mt * 16 + g) * LDAS + k + t;
                af[mt][0] = __float_as_uint(As[buf][r0]);
                af[mt][1] = __float_as_uint(As[buf][r0 + 8 * LDAS]);
                af[mt][2] = __float_as_uint(As[buf][r0 + 4]);
                af[mt][3] = __float_as_uint(As[buf][r0 + 8 * LDAS + 4]);
            }
#pragma unroll
            for (int nt = 0; nt < 4; nt++) {
                int c0 = (warpN * 32 + nt * 8 + g) * LDAS + k + t;
                bf[nt][0] = __float_as_uint(Bs[buf][c0]);
                bf[nt][1] = __float_as_uint(Bs[buf][c0 + 4]);
            }
#pragma unroll
            for (int mt = 0; mt < 4; mt++)
#pragma unroll
                for (int nt = 0; nt < 4; nt++)
                    mma_tf32(acc[mt][nt], af[mt], bf[nt]);
        }
        if (c + 1 < nc) {
            int nb = 1 - buf;
#pragma unroll
            for (int i = 0; i < 2; i++) {
                int m = i ? m1 : m0, kq = i ? kq1 : kq0;
                float4 a = ra[i], b = rb[i];
                a.x = to_tf32(a.x); a.y = to_tf32(a.y); a.z = to_tf32(a.z); a.w = to_tf32(a.w);
                b.x = to_tf32(b.x); b.y = to_tf32(b.y); b.z = to_tf32(b.z); b.w = to_tf32(b.w);
                *(float4*)&As[nb][m * LDAS + kq * 4] = a;
                *(float4*)&Bs[nb][m * LDAS + kq * 4] = b;
            }
            __syncthreads();
        }
    }

    // epilogue: each (mt,nt) frag covers rows {r, r+8} x cols {c, c+1}
#pragma unroll
    for (int mt = 0; mt < 4; mt++) {
        int rlo = rowBase + warpM * 64 + mt * 16 + g;
#pragma unroll
        for (int nt = 0; nt < 4; nt++) {
            int colb = colBase + warpN * 32 + nt * 8 + t * 2;
#pragma unroll
            for (int half = 0; half < 2; half++) {
                int row = rlo + half * 8;
                float v0 = acc[mt][nt][half * 2 + 0];
                float v1 = acc[mt][nt][half * 2 + 1];
                if (EPI == 0) {
                    int which = colb / CDIM;
                    int rem = colb - which * CDIM;
                    int h = rem >> 6, d0 = rem & 63;
                    int bq = row >> 11, n = row & 2047;
                    float scale = (which == 0) ? 0.125f : 1.0f;
                    float* dst = (which == 0 ? qout : (which == 1 ? kout : vout)) +
                                 ((((size_t)bq * HH + h) * NSEQ + n) * DD + d0);
                    float2 o = make_float2(v0 * scale, v1 * scale);
                    *(float2*)dst = o;
                } else if (EPI == 1) {
                    float2 bv = *(const float2*)(bias + colb);
                    float2 rv = *(const float2*)(res + (size_t)row * Nn + colb);
                    float2 o = make_float2(v0 + bv.x + rv.x, v1 + bv.y + rv.y);
                    *(float2*)(C + (size_t)row * Nn + colb) = o;
                } else {
                    float2 bv = *(const float2*)(bias + colb);
                    float u0 = v0 + bv.x, u1 = v1 + bv.y;
                    float2 o;
                    o.x = 0.5f * u0 * (1.0f + erff(u0 * 0.70710678f));
                    o.y = 0.5f * u1 * (1.0f + erff(u1 * 0.70710678f));
                    *(float2*)(C + (size_t)row * Nn + colb) = o;
                }
            }
        }
    }
}

// ---------------- LayerNorm ----------------
__global__ __launch_bounds__(256) void ln_kernel(const float* __restrict__ X,
                                                 const float* __restrict__ gam,
                                                 const float* __restrict__ bet,
                                                 float* __restrict__ out) {
    int row = blockIdx.x;
    const float* xr = X + (size_t)row * CDIM;
    float v[3];
    float s = 0.f, s2 = 0.f;
#pragma unroll
    for (int i = 0; i < 3; i++) {
        v[i] = xr[threadIdx.x + i * 256];
        s += v[i];
        s2 += v[i] * v[i];
    }
#pragma unroll
    for (int o = 16; o > 0; o >>= 1) {
        s  += __shfl_xor_sync(0xffffffffu, s, o);
        s2 += __shfl_xor_sync(0xffffffffu, s2, o);
    }
    __shared__ float ws[8], ws2[8];
    int wid = threadIdx.x >> 5, lane = threadIdx.x & 31;
    if (lane == 0) { ws[wid] = s; ws2[wid] = s2; }
    __syncthreads();
    if (wid == 0) {
        s  = (lane < 8) ? ws[lane] : 0.f;
        s2 = (lane < 8) ? ws2[lane] : 0.f;
#pragma unroll
        for (int o = 4; o > 0; o >>= 1) {
            s  += __shfl_xor_sync(0xffffffffu, s, o);
            s2 += __shfl_xor_sync(0xffffffffu, s2, o);
        }
        if (lane == 0) { ws[0] = s; ws2[0] = s2; }
    }
    __syncthreads();
    float mu   = ws[0] * (1.0f / CDIM);
    float var  = ws2[0] * (1.0f / CDIM) - mu * mu;
    float rstd = rsqrtf(var + 1e-5f);
#pragma unroll
    for (int i = 0; i < 3; i++) {
        int c = threadIdx.x + i * 256;
        out[(size_t)row * CDIM + c] = (v[i] - mu) * rstd * gam[c] + bet[c];
    }
}

// ---------------- Flash attention (fp32, 1 thread per query row) ----------------
#define AT_BN 32
__global__ __launch_bounds__(128) void attn_kernel(const float* __restrict__ Q,
                                                   const float* __restrict__ K,
                                                   const float* __restrict__ V,
                                                   float* __restrict__ O) {
    __shared__ float Ks[AT_BN * DD];
    __shared__ float Vs[AT_BN * DD];
    int bh = blockIdx.y;
    int b = bh / HH, h = bh - b * HH;
    int row = blockIdx.x * 128 + threadIdx.x;

    const float4* qp = (const float4*)(Q + (((size_t)bh * NSEQ) + row) * DD);
    float q[DD];
#pragma unroll
    for (int i = 0; i < 16; i++) {
        float4 t = qp[i];
        q[4 * i + 0] = t.x; q[4 * i + 1] = t.y; q[4 * i + 2] = t.z; q[4 * i + 3] = t.w;
    }

    float acc[DD];
#pragma unroll
    for (int d = 0; d < DD; d++) acc[d] = 0.f;
    float m = -1e30f, l = 0.f;

    const float4* Kb = (const float4*)(K + (size_t)bh * NSEQ * DD);
    const float4* Vb = (const float4*)(V + (size_t)bh * NSEQ * DD);

    for (int t = 0; t < NSEQ / AT_BN; ++t) {
        const float4* ks4 = Kb + t * (AT_BN * DD / 4);
        const float4* vs4 = Vb + t * (AT_BN * DD / 4);
#pragma unroll
        for (int i = 0; i < AT_BN * DD / 4 / 128; i++) {
            ((float4*)Ks)[threadIdx.x + i * 128] = ks4[threadIdx.x + i * 128];
            ((float4*)Vs)[threadIdx.x + i * 128] = vs4[threadIdx.x + i * 128];
        }
        __syncthreads();

        float s[AT_BN];
        float tm = -1e30f;
#pragma unroll
        for (int j = 0; j < AT_BN; j++) {
            const float4* krow = (const float4*)(Ks + j * DD);
            float s0 = 0.f, s1 = 0.f, s2 = 0.f, s3 = 0.f;
#pragma unroll
            for (int i = 0; i < 16; i++) {
                float4 kk = krow[i];
                s0 += q[4 * i + 0] * kk.x;
                s1 += q[4 * i + 1] * kk.y;
                s2 += q[4 * i + 2] * kk.z;
                s3 += q[4 * i + 3] * kk.w;
            }
            s[j] = (s0 + s1) + (s2 + s3);
            tm = fmaxf(tm, s[j]);
        }
        float mn = fmaxf(m, tm);
        float alpha = __expf(m - mn);
        l *= alpha;
#pragma unroll
        for (int d = 0; d < DD; d++) acc[d] *= alpha;
#pragma unroll
        for (int j = 0; j < AT_BN; j++) {
            float p = __expf(s[j] - mn);
            l += p;
            s[j] = p;
        }
        m = mn;
#pragma unroll
        for (int j = 0; j < AT_BN; j++) {
            float p = s[j];
            const float4* vrow = (const float4*)(Vs + j * DD);
#pragma unroll
            for (int i = 0; i < 16; i++) {
                float4 vv = vrow[i];
                acc[4 * i + 0] += p * vv.x;
                acc[4 * i + 1] += p * vv.y;
                acc[4 * i + 2] += p * vv.z;
                acc[4 * i + 3] += p * vv.w;
            }
        }
        __syncthreads();
    }

    float inv = 1.0f / l;
    float* op = O + (((size_t)b * NSEQ) + row) * CDIM + h * DD;
#pragma unroll
    for (int d = 0; d < DD; d++) op[d] = acc[d] * inv;
}

// ---------------- host ----------------
extern "C" void kernel_launch(void* const* d_in, const int* in_sizes, int n_in,
                              void* d_out, int out_size) {
    const float* x      = (const float*)d_in[0];
    const float* ln1_g  = (const float*)d_in[1];
    const float* ln1_b  = (const float*)d_in[2];
    const float* qkv_w  = (const float*)d_in[3];
    const float* proj_w = (const float*)d_in[4];
    const float* proj_b = (const float*)d_in[5];
    const float* ln2_g  = (const float*)d_in[6];
    const float* ln2_b  = (const float*)d_in[7];
    const float* fc1_w  = (const float*)d_in[8];
    const float* fc1_b  = (const float*)d_in[9];
    const float* fc2_w  = (const float*)d_in[10];
    const float* fc2_b  = (const float*)d_in[11];
    float* out = (float*)d_out;

    float *h, *q, *k, *v, *o, *x1, *hid;
    cudaGetSymbolAddress((void**)&h,   g_h);
    cudaGetSymbolAddress((void**)&q,   g_q);
    cudaGetSymbolAddress((void**)&k,   g_k);
    cudaGetSymbolAddress((void**)&v,   g_v);
    cudaGetSymbolAddress((void**)&o,   g_o);
    cudaGetSymbolAddress((void**)&x1,  g_x1);
    cudaGetSymbolAddress((void**)&hid, g_hid);

    // 1. LN1
    ln_kernel<<<MROWS, 256>>>(x, ln1_g, ln1_b, h);
    // 2. QKV GEMM -> scatter q/k/v [B,H,N,D], q scaled by D^-0.5
    gemm_mma<0><<<dim3(3 * CDIM / 128, MROWS / 128), 256>>>(
        h, qkv_w, nullptr, nullptr, nullptr, MROWS, 3 * CDIM, CDIM, q, k, v);
    // 3. flash attention
    attn_kernel<<<dim3(NSEQ / 128, BB * HH), 128>>>(q, k, v, o);
    // 4. proj + bias + residual(x)
    gemm_mma<1><<<dim3(CDIM / 128, MROWS / 128), 256>>>(
        o, proj_w, proj_b, x, x1, MROWS, CDIM, CDIM, nullptr, nullptr, nullptr);
    // 5. LN2
    ln_kernel<<<MROWS, 256>>>(x1, ln2_g, ln2_b, h);
    // 6. FC1 + bias + GELU
    gemm_mma<2><<<dim3(HIDD / 128, MROWS / 128), 256>>>(
        h, fc1_w, fc1_b, nullptr, hid, MROWS, HIDD, CDIM, nullptr, nullptr, nullptr);
    // 7. FC2 + bias + residual(x1)
    gemm_mma<1><<<dim3(CDIM / 128, MROWS / 128), 256>>>(
        hid, fc2_w, fc2_b, x1, out, MROWS, CDIM, HIDD, nullptr, nullptr, nullptr);
}

// round 4
// speedup vs baseline: 3.1800x; 2.0192x over previous
#include <cuda_runtime.h>
#include <cstdint>
#include <math.h>

#define BB 4
#define NSEQ 2048
#define CDIM 768
#define HH 12
#define DD 64
#define HIDD 3072
#define MROWS (BB * NSEQ)   // 8192

// ---------------- scratch ----------------
__device__ float g_h[MROWS * CDIM];
__device__ float g_q[MROWS * CDIM];
__device__ float g_k[MROWS * CDIM];
__device__ float g_v[MROWS * CDIM];
__device__ float g_o[MROWS * CDIM];
__device__ float g_x1[MROWS * CDIM];
__device__ float g_hid[MROWS * HIDD];

__device__ __forceinline__ float to_tf32(float x) {
    float y;
    asm("cvt.rna.tf32.f32 %0, %1;" : "=f"(y) : "f"(x));
    return y;
}
__device__ __forceinline__ uint32_t smem_u32(const void* p) {
    uint32_t a;
    asm("{ .reg .u64 t; cvta.to.shared.u64 t, %1; cvt.u32.u64 %0, t; }" : "=r"(a) : "l"(p));
    return a;
}
__device__ __forceinline__ void mma_tf32(float* d, const uint32_t* a, const uint32_t* b) {
    asm volatile(
        "mma.sync.aligned.m16n8k8.row.col.f32.tf32.tf32.f32 "
        "{%0,%1,%2,%3}, {%4,%5,%6,%7}, {%8,%9}, {%0,%1,%2,%3};"
        : "+f"(d[0]), "+f"(d[1]), "+f"(d[2]), "+f"(d[3])
        : "r"(a[0]), "r"(a[1]), "r"(a[2]), "r"(a[3]), "r"(b[0]), "r"(b[1]));
}
__device__ __forceinline__ void ldsm4(uint32_t* r, uint32_t addr) {
    asm volatile("ldmatrix.sync.aligned.m8n8.x4.shared.b16 {%0,%1,%2,%3}, [%4];"
                 : "=r"(r[0]), "=r"(r[1]), "=r"(r[2]), "=r"(r[3]) : "r"(addr));
}

// ---------------- tensor-core TF32 GEMM: C[M,Nn] = A[M,K] * W[Nn,K]^T ----------------
// BM=BN=128, BK=16, 256 threads (8 warps 2x4), warp tile 64x32, m16n8k8, ldmatrix feeds.
#define LDAS 20

template <int EPI>
__global__ __launch_bounds__(256) void gemm_mma(
    const float* __restrict__ A, const float* __restrict__ W,
    const float* __restrict__ bias, const float* __restrict__ res,
    float* __restrict__ C, int M, int Nn, int K,
    float* __restrict__ qout, float* __restrict__ kout, float* __restrict__ vout) {
    __shared__ float As[2][128 * LDAS];
    __shared__ float Bs[2][128 * LDAS];
    int tid = threadIdx.x, lane = tid & 31, wid = tid >> 5;
    int warpM = wid & 1, warpN = wid >> 1;
    int g = lane >> 2, t = lane & 3;
    int rowBase = blockIdx.y * 128, colBase = blockIdx.x * 128;

    float acc[4][4][4];
#pragma unroll
    for (int i = 0; i < 4; i++)
#pragma unroll
        for (int j = 0; j < 4; j++)
#pragma unroll
            for (int e = 0; e < 4; e++) acc[i][j][e] = 0.f;

    // ldmatrix lane->row mapping addresses (bytes, within buffer 0)
    const uint32_t aB = smem_u32(&As[0][0]) +
        4 * ((warpM * 64 + (lane & 15)) * LDAS + ((lane >> 4) << 2));
    const uint32_t bB = smem_u32(&Bs[0][0]) +
        4 * ((warpN * 32 + (lane & 7) + ((lane >> 4) << 3)) * LDAS + (((lane >> 3) & 1) << 2));
    const uint32_t bufStride = 128 * LDAS * 4;

    float4 ra[2], rb[2];
    const int m0 = (tid * 2) >> 2, kq0 = (tid * 2) & 3;
    const int m1 = (tid * 2 + 1) >> 2, kq1 = (tid * 2 + 1) & 3;

    int nc = K >> 4;
    {
        const float* Ab = A + (size_t)rowBase * K;
        const float* Wb = W + (size_t)colBase * K;
        ra[0] = *(const float4*)(Ab + (size_t)m0 * K + kq0 * 4);
        ra[1] = *(const float4*)(Ab + (size_t)m1 * K + kq1 * 4);
        rb[0] = *(const float4*)(Wb + (size_t)m0 * K + kq0 * 4);
        rb[1] = *(const float4*)(Wb + (size_t)m1 * K + kq1 * 4);
    }
#pragma unroll
    for (int i = 0; i < 2; i++) {
        int m = i ? m1 : m0, kq = i ? kq1 : kq0;
        float4 a = ra[i], b = rb[i];
        a.x = to_tf32(a.x); a.y = to_tf32(a.y); a.z = to_tf32(a.z); a.w = to_tf32(a.w);
        b.x = to_tf32(b.x); b.y = to_tf32(b.y); b.z = to_tf32(b.z); b.w = to_tf32(b.w);
        *(float4*)&As[0][m * LDAS + kq * 4] = a;
        *(float4*)&Bs[0][m * LDAS + kq * 4] = b;
    }
    __syncthreads();

    for (int c = 0; c < nc; c++) {
        int buf = c & 1;
        if (c + 1 < nc) {
            const float* Ab = A + (size_t)rowBase * K + (c + 1) * 16;
            const float* Wb = W + (size_t)colBase * K + (c + 1) * 16;
            ra[0] = *(const float4*)(Ab + (size_t)m0 * K + kq0 * 4);
            ra[1] = *(const float4*)(Ab + (size_t)m1 * K + kq1 * 4);
            rb[0] = *(const float4*)(Wb + (size_t)m0 * K + kq0 * 4);
            rb[1] = *(const float4*)(Wb + (size_t)m1 * K + kq1 * 4);
        }
        uint32_t aBuf = aB + buf * bufStride;
        uint32_t bBuf = bB + buf * bufStride;
#pragma unroll
        for (int ks = 0; ks < 2; ks++) {
            uint32_t af[4][4], bf[2][4];
#pragma unroll
            for (int mt = 0; mt < 4; mt++)
                ldsm4(af[mt], aBuf + 4 * (mt * 16 * LDAS + ks * 8));
#pragma unroll
            for (int p = 0; p < 2; p++)
                ldsm4(bf[p], bBuf + 4 * (p * 16 * LDAS + ks * 8));
#pragma unroll
            for (int mt = 0; mt < 4; mt++)
#pragma unroll
                for (int nt = 0; nt < 4; nt++)
                    mma_tf32(acc[mt][nt], af[mt], &bf[nt >> 1][(nt & 1) * 2]);
        }
        if (c + 1 < nc) {
            int nb = 1 - buf;
#pragma unroll
            for (int i = 0; i < 2; i++) {
                int m = i ? m1 : m0, kq = i ? kq1 : kq0;
                float4 a = ra[i], b = rb[i];
                a.x = to_tf32(a.x); a.y = to_tf32(a.y); a.z = to_tf32(a.z); a.w = to_tf32(a.w);
                b.x = to_tf32(b.x); b.y = to_tf32(b.y); b.z = to_tf32(b.z); b.w = to_tf32(b.w);
                *(float4*)&As[nb][m * LDAS + kq * 4] = a;
                *(float4*)&Bs[nb][m * LDAS + kq * 4] = b;
            }
            __syncthreads();
        }
    }

#pragma unroll
    for (int mt = 0; mt < 4; mt++) {
        int rlo = rowBase + warpM * 64 + mt * 16 + g;
#pragma unroll
        for (int nt = 0; nt < 4; nt++) {
            int colb = colBase + warpN * 32 + nt * 8 + t * 2;
#pragma unroll
            for (int half = 0; half < 2; half++) {
                int row = rlo + half * 8;
                float v0 = acc[mt][nt][half * 2 + 0];
                float v1 = acc[mt][nt][half * 2 + 1];
                if (EPI == 0) {
                    int which = colb / CDIM;
                    int rem = colb - which * CDIM;
                    int h = rem >> 6, d0 = rem & 63;
                    int bq = row >> 11, n = row & 2047;
                    float scale = (which == 0) ? 0.125f : 1.0f;
                    float* dst = (which == 0 ? qout : (which == 1 ? kout : vout)) +
                                 ((((size_t)bq * HH + h) * NSEQ + n) * DD + d0);
                    *(float2*)dst = make_float2(v0 * scale, v1 * scale);
                } else if (EPI == 1) {
                    float2 bv = *(const float2*)(bias + colb);
                    float2 rv = *(const float2*)(res + (size_t)row * Nn + colb);
                    *(float2*)(C + (size_t)row * Nn + colb) =
                        make_float2(v0 + bv.x + rv.x, v1 + bv.y + rv.y);
                } else {
                    float2 bv = *(const float2*)(bias + colb);
                    float u0 = v0 + bv.x, u1 = v1 + bv.y;
                    float2 o;
                    o.x = 0.5f * u0 * (1.0f + erff(u0 * 0.70710678f));
                    o.y = 0.5f * u1 * (1.0f + erff(u1 * 0.70710678f));
                    *(float2*)(C + (size_t)row * Nn + colb) = o;
                }
            }
        }
    }
}

// ---------------- LayerNorm ----------------
__global__ __launch_bounds__(256) void ln_kernel(const float* __restrict__ X,
                                                 const float* __restrict__ gam,
                                                 const float* __restrict__ bet,
                                                 float* __restrict__ out) {
    int row = blockIdx.x;
    const float* xr = X + (size_t)row * CDIM;
    float v[3];
    float s = 0.f, s2 = 0.f;
#pragma unroll
    for (int i = 0; i < 3; i++) {
        v[i] = xr[threadIdx.x + i * 256];
        s += v[i];
        s2 += v[i] * v[i];
    }
#pragma unroll
    for (int o = 16; o > 0; o >>= 1) {
        s  += __shfl_xor_sync(0xffffffffu, s, o);
        s2 += __shfl_xor_sync(0xffffffffu, s2, o);
    }
    __shared__ float ws[8], ws2[8];
    int wid = threadIdx.x >> 5, lane = threadIdx.x & 31;
    if (lane == 0) { ws[wid] = s; ws2[wid] = s2; }
    __syncthreads();
    if (wid == 0) {
        s  = (lane < 8) ? ws[lane] : 0.f;
        s2 = (lane < 8) ? ws2[lane] : 0.f;
#pragma unroll
        for (int o = 4; o > 0; o >>= 1) {
            s  += __shfl_xor_sync(0xffffffffu, s, o);
            s2 += __shfl_xor_sync(0xffffffffu, s2, o);
        }
        if (lane == 0) { ws[0] = s; ws2[0] = s2; }
    }
    __syncthreads();
    float mu   = ws[0] * (1.0f / CDIM);
    float var  = ws2[0] * (1.0f / CDIM) - mu * mu;
    float rstd = rsqrtf(var + 1e-5f);
#pragma unroll
    for (int i = 0; i < 3; i++) {
        int c = threadIdx.x + i * 256;
        out[(size_t)row * CDIM + c] = (v[i] - mu) * rstd * gam[c] + bet[c];
    }
}

// ---------------- Tensor-core flash attention ----------------
// block: 128 queries x full head. 8 warps; warp = 16 query rows.
// key tiles of 64. All MMA tf32 m16n8k8 via ldmatrix.
#define LDK 68
// smem float offsets
#define OFF_Q 0
#define OFF_K (128 * LDK)
#define OFF_V (OFF_K + 64 * LDK)
#define OFF_P (OFF_V + 64 * LDK)
#define ATT_SMEM ((OFF_P + 128 * LDK) * 4)   // 104448 bytes

__global__ __launch_bounds__(256) void attn_mma(const float* __restrict__ Q,
                                                const float* __restrict__ K,
                                                const float* __restrict__ V,
                                                float* __restrict__ O) {
    extern __shared__ float smf[];
    uint32_t sbase = smem_u32(smf);
    int tid = threadIdx.x, lane = tid & 31, wm = tid >> 5;
    int g = lane >> 2, t = lane & 3;
    int bh = blockIdx.y;
    int b = bh / HH, h = bh - b * HH;
    int qbase = blockIdx.x * 128;

    // stage Q (tf32)
    {
        const float* Qg = Q + ((size_t)bh * NSEQ + qbase) * DD;
#pragma unroll
        for (int i = 0; i < 8; i++) {
            int idx = tid + i * 256;
            int r = idx >> 4, c4 = idx & 15;
            float4 vv = *(const float4*)(Qg + (size_t)r * DD + c4 * 4);
            vv.x = to_tf32(vv.x); vv.y = to_tf32(vv.y); vv.z = to_tf32(vv.z); vv.w = to_tf32(vv.w);
            *(float4*)&smf[OFF_Q + r * LDK + c4 * 4] = vv;
        }
    }

    float acc_o[8][4];
#pragma unroll
    for (int i = 0; i < 8; i++)
#pragma unroll
        for (int j = 0; j < 4; j++) acc_o[i][j] = 0.f;
    float m0r = -1e30f, m1r = -1e30f, l0 = 0.f, l1 = 0.f;

    // ldmatrix addresses
    const uint32_t qA = sbase + 4 * (OFF_Q + (wm * 16 + (lane & 15)) * LDK + ((lane >> 4) << 2));
    const uint32_t kA = sbase + 4 * (OFF_K + ((lane & 7) + ((lane >> 4) << 3)) * LDK + (((lane >> 3) & 1) << 2));
    const uint32_t vA = sbase + 4 * (OFF_V + ((lane & 7) + ((lane >> 4) << 3)) * LDK + (((lane >> 3) & 1) << 2));
    const uint32_t pA = sbase + 4 * (OFF_P + (wm * 16 + (lane & 15)) * LDK + ((lane >> 4) << 2));

    const int vkey = tid & 63, vdb = (tid >> 6) * 16;

    for (int kt = 0; kt < NSEQ / 64; kt++) {
        // stage K tile [64 keys][64 d]
        const float* Kg = K + ((size_t)bh * NSEQ + kt * 64) * DD;
#pragma unroll
        for (int i = 0; i < 4; i++) {
            int idx = tid + i * 256;
            int r = idx >> 4, c4 = idx & 15;
            float4 vv = *(const float4*)(Kg + (size_t)r * DD + c4 * 4);
            vv.x = to_tf32(vv.x); vv.y = to_tf32(vv.y); vv.z = to_tf32(vv.z); vv.w = to_tf32(vv.w);
            *(float4*)&smf[OFF_K + r * LDK + c4 * 4] = vv;
        }
        // stage V tile transposed: Vs[d][key]
        const float* Vg = V + ((size_t)bh * NSEQ + kt * 64) * DD;
#pragma unroll
        for (int i = 0; i < 4; i++) {
            float4 vv = *(const float4*)(Vg + (size_t)vkey * DD + vdb + 4 * i);
            smf[OFF_V + (vdb + 4 * i + 0) * LDK + vkey] = to_tf32(vv.x);
            smf[OFF_V + (vdb + 4 * i + 1) * LDK + vkey] = to_tf32(vv.y);
            smf[OFF_V + (vdb + 4 * i + 2) * LDK + vkey] = to_tf32(vv.z);
            smf[OFF_V + (vdb + 4 * i + 3) * LDK + vkey] = to_tf32(vv.w);
        }
        __syncthreads();

        // S = Q K^T  (warp: 16 rows x 64 keys)
        float s[8][4];
#pragma unroll
        for (int i = 0; i < 8; i++)
#pragma unroll
            for (int j = 0; j < 4; j++) s[i][j] = 0.f;
#pragma unroll
        for (int ks = 0; ks < 8; ks++) {
            uint32_t qa[4], kb[4][4];
            ldsm4(qa, qA + ks * 32);
#pragma unroll
            for (int p = 0; p < 4; p++)
                ldsm4(kb[p], kA + 4 * (p * 16 * LDK + ks * 8));
#pragma unroll
            for (int nt = 0; nt < 8; nt++)
                mma_tf32(s[nt], qa, &kb[nt >> 1][(nt & 1) * 2]);
        }

        // online softmax (rows g, g+8 of warp tile)
        float mx0 = -1e30f, mx1 = -1e30f;
#pragma unroll
        for (int nt = 0; nt < 8; nt++) {
            mx0 = fmaxf(mx0, fmaxf(s[nt][0], s[nt][1]));
            mx1 = fmaxf(mx1, fmaxf(s[nt][2], s[nt][3]));
        }
        mx0 = fmaxf(mx0, __shfl_xor_sync(0xffffffffu, mx0, 1));
        mx0 = fmaxf(mx0, __shfl_xor_sync(0xffffffffu, mx0, 2));
        mx1 = fmaxf(mx1, __shfl_xor_sync(0xffffffffu, mx1, 1));
        mx1 = fmaxf(mx1, __shfl_xor_sync(0xffffffffu, mx1, 2));
        float nm0 = fmaxf(m0r, mx0), nm1 = fmaxf(m1r, mx1);
        float al0 = __expf(m0r - nm0), al1 = __expf(m1r - nm1);
        float ts0 = 0.f, ts1 = 0.f;
        uint32_t pw0 = pA - (uint32_t)(4 * ((lane & 15) * LDK + ((lane >> 4) << 2)));  // row base of warp tile in Ps
#pragma unroll
        for (int nt = 0; nt < 8; nt++) {
            float p00 = __expf(s[nt][0] - nm0);
            float p01 = __expf(s[nt][1] - nm0);
            float p10 = __expf(s[nt][2] - nm1);
            float p11 = __expf(s[nt][3] - nm1);
            ts0 += p00 + p01; ts1 += p10 + p11;
            float2 v0 = make_float2(to_tf32(p00), to_tf32(p01));
            float2 v1 = make_float2(to_tf32(p10), to_tf32(p11));
            *(float2*)((char*)smf + (pw0 - sbase) + sbase * 0 +
                       4 * ((size_t)0) + 0 + 4 * (g * LDK + nt * 8 + 2 * t)) = v0;   // rows g
            *(float2*)((char*)smf + (pw0 - sbase) + 4 * ((g + 8) * LDK + nt * 8 + 2 * t)) = v1;
        }
        ts0 += __shfl_xor_sync(0xffffffffu, ts0, 1);
        ts0 += __shfl_xor_sync(0xffffffffu, ts0, 2);
        ts1 += __shfl_xor_sync(0xffffffffu, ts1, 1);
        ts1 += __shfl_xor_sync(0xffffffffu, ts1, 2);
        l0 = l0 * al0 + ts0;
        l1 = l1 * al1 + ts1;
        m0r = nm0; m1r = nm1;
#pragma unroll
        for (int nt = 0; nt < 8; nt++) {
            acc_o[nt][0] *= al0; acc_o[nt][1] *= al0;
            acc_o[nt][2] *= al1; acc_o[nt][3] *= al1;
        }

        // O += P V   (A = Ps rows of own warp; B = Vs[d][key])
#pragma unroll
        for (int kk = 0; kk < 8; kk++) {
            uint32_t pa[4], vb[4][4];
            ldsm4(pa, pA + kk * 32);
#pragma unroll
            for (int p = 0; p < 4; p++)
                ldsm4(vb[p], vA + 4 * (p * 16 * LDK + kk * 8));
#pragma unroll
            for (int nt = 0; nt < 8; nt++)
                mma_tf32(acc_o[nt], pa, &vb[nt >> 1][(nt & 1) * 2]);
        }
        __syncthreads();
    }

    float inv0 = 1.0f / l0, inv1 = 1.0f / l1;
    int row0 = qbase + wm * 16 + g;
    float* Ob = O + ((size_t)b * NSEQ) * CDIM + h * DD;
#pragma unroll
    for (int nt = 0; nt < 8; nt++) {
        int col = nt * 8 + 2 * t;
        *(float2*)(Ob + (size_t)row0 * CDIM + col) =
            make_float2(acc_o[nt][0] * inv0, acc_o[nt][1] * inv0);
        *(float2*)(Ob + (size_t)(row0 + 8) * CDIM + col) =
            make_float2(acc_o[nt][2] * inv1, acc_o[nt][3] * inv1);
    }
}

// ---------------- host ----------------
extern "C" void kernel_launch(void* const* d_in, const int* in_sizes, int n_in,
                              void* d_out, int out_size) {
    const float* x      = (const float*)d_in[0];
    const float* ln1_g  = (const float*)d_in[1];
    const float* ln1_b  = (const float*)d_in[2];
    const float* qkv_w  = (const float*)d_in[3];
    const float* proj_w = (const float*)d_in[4];
    const float* proj_b = (const float*)d_in[5];
    const float* ln2_g  = (const float*)d_in[6];
    const float* ln2_b  = (const float*)d_in[7];
    const float* fc1_w  = (const float*)d_in[8];
    const float* fc1_b  = (const float*)d_in[9];
    const float* fc2_w  = (const float*)d_in[10];
    const float* fc2_b  = (const float*)d_in[11];
    float* out = (float*)d_out;

    float *h, *q, *k, *v, *o, *x1, *hid;
    cudaGetSymbolAddress((void**)&h,   g_h);
    cudaGetSymbolAddress((void**)&q,   g_q);
    cudaGetSymbolAddress((void**)&k,   g_k);
    cudaGetSymbolAddress((void**)&v,   g_v);
    cudaGetSymbolAddress((void**)&o,   g_o);
    cudaGetSymbolAddress((void**)&x1,  g_x1);
    cudaGetSymbolAddress((void**)&hid, g_hid);

    cudaFuncSetAttribute(attn_mma, cudaFuncAttributeMaxDynamicSharedMemorySize, ATT_SMEM);

    ln_kernel<<<MROWS, 256>>>(x, ln1_g, ln1_b, h);
    gemm_mma<0><<<dim3(3 * CDIM / 128, MROWS / 128), 256>>>(
        h, qkv_w, nullptr, nullptr, nullptr, MROWS, 3 * CDIM, CDIM, q, k, v);
    attn_mma<<<dim3(NSEQ / 128, BB * HH), 256, ATT_SMEM>>>(q, k, v, o);
    gemm_mma<1><<<dim3(CDIM / 128, MROWS / 128), 256>>>(
        o, proj_w, proj_b, x, x1, MROWS, CDIM, CDIM, nullptr, nullptr, nullptr);
    ln_kernel<<<MROWS, 256>>>(x1, ln2_g, ln2_b, h);
    gemm_mma<2><<<dim3(HIDD / 128, MROWS / 128), 256>>>(
        h, fc1_w, fc1_b, nullptr, hid, MROWS, HIDD, CDIM, nullptr, nullptr, nullptr);
    gemm_mma<1><<<dim3(CDIM / 128, MROWS / 128), 256>>>(
        hid, fc2_w, fc2_b, x1, out, MROWS, CDIM, HIDD, nullptr, nullptr, nullptr);
}

// round 5
// speedup vs baseline: 4.3588x; 1.3707x over previous
#include <cuda_runtime.h>
#include <cstdint>
#include <math.h>

#define BB 4
#define NSEQ 2048
#define CDIM 768
#define HH 12
#define DD 64
#define HIDD 3072
#define MROWS (BB * NSEQ)   // 8192

// ---------------- scratch ----------------
__device__ float g_h[MROWS * CDIM];
__device__ float g_q[MROWS * CDIM];
__device__ float g_k[MROWS * CDIM];
__device__ float g_v[MROWS * CDIM];
__device__ float g_o[MROWS * CDIM];
__device__ float g_x1[MROWS * CDIM];
__device__ float g_hid[MROWS * HIDD];
// tf32-rounded weights
__device__ float g_wqkv[3 * CDIM * CDIM];
__device__ float g_wproj[CDIM * CDIM];
__device__ float g_wfc1[HIDD * CDIM];
__device__ float g_wfc2[CDIM * HIDD];

__device__ __forceinline__ float to_tf32(float x) {
    float y;
    asm("cvt.rna.tf32.f32 %0, %1;" : "=f"(y) : "f"(x));
    return y;
}
__device__ __forceinline__ uint32_t smem_u32(const void* p) {
    uint32_t a;
    asm("{ .reg .u64 t; cvta.to.shared.u64 t, %1; cvt.u32.u64 %0, t; }" : "=r"(a) : "l"(p));
    return a;
}
__device__ __forceinline__ void mma_tf32(float* d, const uint32_t* a, const uint32_t* b) {
    asm volatile(
        "mma.sync.aligned.m16n8k8.row.col.f32.tf32.tf32.f32 "
        "{%0,%1,%2,%3}, {%4,%5,%6,%7}, {%8,%9}, {%0,%1,%2,%3};"
        : "+f"(d[0]), "+f"(d[1]), "+f"(d[2]), "+f"(d[3])
        : "r"(a[0]), "r"(a[1]), "r"(a[2]), "r"(a[3]), "r"(b[0]), "r"(b[1]));
}
__device__ __forceinline__ void ldsm4(uint32_t* r, uint32_t addr) {
    asm volatile("ldmatrix.sync.aligned.m8n8.x4.shared.b16 {%0,%1,%2,%3}, [%4];"
                 : "=r"(r[0]), "=r"(r[1]), "=r"(r[2]), "=r"(r[3]) : "r"(addr));
}
__device__ __forceinline__ void cp16(uint32_t dst, const float* src) {
    asm volatile("cp.async.cg.shared.global [%0], [%1], 16;"
                 :: "r"(dst), "l"(__cvta_generic_to_global(src)));
}
#define CP_COMMIT() asm volatile("cp.async.commit_group;" ::: "memory")
#define CP_WAIT1()  asm volatile("cp.async.wait_group 1;" ::: "memory")

// ---------------- weight tf32 pre-round ----------------
__global__ __launch_bounds__(256) void wcvt_kernel(
    const float* s0, float* d0, int n0, const float* s1, float* d1, int n1,
    const float* s2, float* d2, int n2, const float* s3, float* d3, int n3) {
    const float* s; float* d; int n;
    switch (blockIdx.y) {
        case 0: s = s0; d = d0; n = n0; break;
        case 1: s = s1; d = d1; n = n1; break;
        case 2: s = s2; d = d2; n = n2; break;
        default: s = s3; d = d3; n = n3; break;
    }
    int i = (blockIdx.x * 256 + threadIdx.x) * 4;
    if (i < n) {
        float4 v = *(const float4*)(s + i);
        v.x = to_tf32(v.x); v.y = to_tf32(v.y); v.z = to_tf32(v.z); v.w = to_tf32(v.w);
        *(float4*)(d + i) = v;
    }
}

// ---------------- cp.async tensor-core GEMM: C = A[M,K] * W[Nn,K]^T ----------------
// BM=BN=128, BK=32, 3 stages, 256 threads (8 warps 2x4), warp tile 64x32.
// Inputs MUST already be tf32-rounded. Swizzled smem (c16 ^= r&7).
#define GS 3
#define STG_B 32768            // A 16KB + B 16KB per stage
#define GEMM_SMEM (GS * STG_B) // 98304

template <int EPI>
__global__ __launch_bounds__(256) void gemm_cp(
    const float* __restrict__ A, const float* __restrict__ W,
    const float* __restrict__ bias, const float* __restrict__ res,
    float* __restrict__ C, int M, int Nn, int K,
    float* __restrict__ qout, float* __restrict__ kout, float* __restrict__ vout) {
    extern __shared__ char sm[];
    uint32_t sb = smem_u32(sm);
    int tid = threadIdx.x, lane = tid & 31, wid = tid >> 5;
    int warpM = wid & 1, warpN = wid >> 1;
    int g = lane >> 2, t = lane & 3;
    int rowBase = blockIdx.y * 128, colBase = blockIdx.x * 128;

    float acc[4][4][4];
#pragma unroll
    for (int i = 0; i < 4; i++)
#pragma unroll
        for (int j = 0; j < 4; j++)
#pragma unroll
            for (int e = 0; e < 4; e++) acc[i][j][e] = 0.f;

    // staging map: thread handles rows r0+32i, fixed 16B column
    const int r0 = tid >> 3;
    const int c16 = tid & 7;
    const uint32_t csw = (uint32_t)((c16 ^ (r0 & 7)) << 4);
    const float* Ab = A + (size_t)rowBase * K + c16 * 4;
    const float* Wb = W + (size_t)colBase * K + c16 * 4;

    // ldmatrix feed addresses
    const int r7 = lane & 7;
    const int hiA = lane >> 4;
    const int hiB = (lane >> 3) & 1;
    uint32_t rbA[4], rbB[2];
#pragma unroll
    for (int mt = 0; mt < 4; mt++)
        rbA[mt] = (uint32_t)((warpM * 64 + mt * 16 + (lane & 15)) * 128);
#pragma unroll
    for (int p = 0; p < 2; p++)
        rbB[p] = (uint32_t)((warpN * 32 + p * 16 + (lane & 7) + ((lane >> 4) << 3)) * 128) + 16384;

    const int nc = K >> 5;
    // prologue: stages 0..GS-2
#pragma unroll
    for (int s = 0; s < GS - 1; s++) {
        uint32_t sA = sb + s * STG_B;
        const float* Ac = Ab + s * 32;
        const float* Wc = Wb + s * 32;
#pragma unroll
        for (int i = 0; i < 4; i++) {
            int r = r0 + i * 32;
            cp16(sA + r * 128 + csw, Ac + (size_t)r * K);
            cp16(sA + 16384 + r * 128 + csw, Wc + (size_t)r * K);
        }
        CP_COMMIT();
    }

    for (int c = 0; c < nc; c++) {
        CP_WAIT1();
        __syncthreads();
        // issue chunk c+GS-1 (or empty group)
        int nxt = c + GS - 1;
        if (nxt < nc) {
            uint32_t sA = sb + (nxt % GS) * STG_B;
            const float* Ac = Ab + nxt * 32;
            const float* Wc = Wb + nxt * 32;
#pragma unroll
            for (int i = 0; i < 4; i++) {
                int r = r0 + i * 32;
                cp16(sA + r * 128 + csw, Ac + (size_t)r * K);
                cp16(sA + 16384 + r * 128 + csw, Wc + (size_t)r * K);
            }
        }
        CP_COMMIT();
        // compute chunk c
        uint32_t stg = sb + (c % GS) * STG_B;
#pragma unroll
        for (int ks = 0; ks < 4; ks++) {
            uint32_t colA = (uint32_t)((((2 * ks + hiA) ^ r7)) << 4);
            uint32_t colB = (uint32_t)((((2 * ks + hiB) ^ r7)) << 4);
            uint32_t af[4][4], bf[2][4];
#pragma unroll
            for (int mt = 0; mt < 4; mt++) ldsm4(af[mt], stg + rbA[mt] + colA);
#pragma unroll
            for (int p = 0; p < 2; p++) ldsm4(bf[p], stg + rbB[p] + colB);
#pragma unroll
            for (int mt = 0; mt < 4; mt++)
#pragma unroll
                for (int nt = 0; nt < 4; nt++)
                    mma_tf32(acc[mt][nt], af[mt], &bf[nt >> 1][(nt & 1) * 2]);
        }
    }

#pragma unroll
    for (int mt = 0; mt < 4; mt++) {
        int rlo = rowBase + warpM * 64 + mt * 16 + g;
#pragma unroll
        for (int nt = 0; nt < 4; nt++) {
            int colb = colBase + warpN * 32 + nt * 8 + t * 2;
#pragma unroll
            for (int half = 0; half < 2; half++) {
                int row = rlo + half * 8;
                float v0 = acc[mt][nt][half * 2 + 0];
                float v1 = acc[mt][nt][half * 2 + 1];
                if (EPI == 0) {
                    int which = colb / CDIM;
                    int rem = colb - which * CDIM;
                    int h = rem >> 6, d0 = rem & 63;
                    int bq = row >> 11, n = row & 2047;
                    float scale = (which == 0) ? 0.125f : 1.0f;
                    float* dst = (which == 0 ? qout : (which == 1 ? kout : vout)) +
                                 ((((size_t)bq * HH + h) * NSEQ + n) * DD + d0);
                    *(float2*)dst = make_float2(to_tf32(v0 * scale), to_tf32(v1 * scale));
                } else if (EPI == 1) {
                    float2 bv = *(const float2*)(bias + colb);
                    float2 rv = *(const float2*)(res + (size_t)row * Nn + colb);
                    *(float2*)(C + (size_t)row * Nn + colb) =
                        make_float2(v0 + bv.x + rv.x, v1 + bv.y + rv.y);
                } else {
                    float2 bv = *(const float2*)(bias + colb);
                    float u0 = v0 + bv.x, u1 = v1 + bv.y;
                    float2 o;
                    o.x = to_tf32(0.5f * u0 * (1.0f + erff(u0 * 0.70710678f)));
                    o.y = to_tf32(0.5f * u1 * (1.0f + erff(u1 * 0.70710678f)));
                    *(float2*)(C + (size_t)row * Nn + colb) = o;
                }
            }
        }
    }
}

// ---------------- LayerNorm (tf32-rounded output) ----------------
__global__ __launch_bounds__(256) void ln_kernel(const float* __restrict__ X,
                                                 const float* __restrict__ gam,
                                                 const float* __restrict__ bet,
                                                 float* __restrict__ out) {
    int row = blockIdx.x;
    const float* xr = X + (size_t)row * CDIM;
    float v[3];
    float s = 0.f, s2 = 0.f;
#pragma unroll
    for (int i = 0; i < 3; i++) {
        v[i] = xr[threadIdx.x + i * 256];
        s += v[i];
        s2 += v[i] * v[i];
    }
#pragma unroll
    for (int o = 16; o > 0; o >>= 1) {
        s  += __shfl_xor_sync(0xffffffffu, s, o);
        s2 += __shfl_xor_sync(0xffffffffu, s2, o);
    }
    __shared__ float ws[8], ws2[8];
    int wid = threadIdx.x >> 5, lane = threadIdx.x & 31;
    if (lane == 0) { ws[wid] = s; ws2[wid] = s2; }
    __syncthreads();
    if (wid == 0) {
        s  = (lane < 8) ? ws[lane] : 0.f;
        s2 = (lane < 8) ? ws2[lane] : 0.f;
#pragma unroll
        for (int o = 4; o > 0; o >>= 1) {
            s  += __shfl_xor_sync(0xffffffffu, s, o);
            s2 += __shfl_xor_sync(0xffffffffu, s2, o);
        }
        if (lane == 0) { ws[0] = s; ws2[0] = s2; }
    }
    __syncthreads();
    float mu   = ws[0] * (1.0f / CDIM);
    float var  = ws2[0] * (1.0f / CDIM) - mu * mu;
    float rstd = rsqrtf(var + 1e-5f);
#pragma unroll
    for (int i = 0; i < 3; i++) {
        int c = threadIdx.x + i * 256;
        out[(size_t)row * CDIM + c] = to_tf32((v[i] - mu) * rstd * gam[c] + bet[c]);
    }
}

// ---------------- Tensor-core flash attention (inputs pre-rounded) ----------------
#define LDK 68
#define OFF_Q 0
#define OFF_K (128 * LDK)
#define OFF_V (OFF_K + 64 * LDK)
#define OFF_P (OFF_V + 64 * LDK)
#define ATT_SMEM ((OFF_P + 128 * LDK) * 4)

__global__ __launch_bounds__(256) void attn_mma(const float* __restrict__ Q,
                                                const float* __restrict__ K,
                                                const float* __restrict__ V,
                                                float* __restrict__ O) {
    extern __shared__ float smf[];
    uint32_t sbase = smem_u32(smf);
    int tid = threadIdx.x, lane = tid & 31, wm = tid >> 5;
    int g = lane >> 2, t = lane & 3;
    int bh = blockIdx.y;
    int b = bh / HH, h = bh - b * HH;
    int qbase = blockIdx.x * 128;

    {
        const float* Qg = Q + ((size_t)bh * NSEQ + qbase) * DD;
#pragma unroll
        for (int i = 0; i < 8; i++) {
            int idx = tid + i * 256;
            int r = idx >> 4, c4 = idx & 15;
            *(float4*)&smf[OFF_Q + r * LDK + c4 * 4] =
                *(const float4*)(Qg + (size_t)r * DD + c4 * 4);
        }
    }

    float acc_o[8][4];
#pragma unroll
    for (int i = 0; i < 8; i++)
#pragma unroll
        for (int j = 0; j < 4; j++) acc_o[i][j] = 0.f;
    float m0r = -1e30f, m1r = -1e30f, l0 = 0.f, l1 = 0.f;

    const uint32_t qA = sbase + 4 * (OFF_Q + (wm * 16 + (lane & 15)) * LDK + ((lane >> 4) << 2));
    const uint32_t kA = sbase + 4 * (OFF_K + ((lane & 7) + ((lane >> 4) << 3)) * LDK + (((lane >> 3) & 1) << 2));
    const uint32_t vA = sbase + 4 * (OFF_V + ((lane & 7) + ((lane >> 4) << 3)) * LDK + (((lane >> 3) & 1) << 2));
    const uint32_t pA = sbase + 4 * (OFF_P + (wm * 16 + (lane & 15)) * LDK + ((lane >> 4) << 2));

    const int vkey = tid & 63, vdb = (tid >> 6) * 16;

    for (int kt = 0; kt < NSEQ / 64; kt++) {
        const float* Kg = K + ((size_t)bh * NSEQ + kt * 64) * DD;
#pragma unroll
        for (int i = 0; i < 4; i++) {
            int idx = tid + i * 256;
            int r = idx >> 4, c4 = idx & 15;
            *(float4*)&smf[OFF_K + r * LDK + c4 * 4] =
                *(const float4*)(Kg + (size_t)r * DD + c4 * 4);
        }
        const float* Vg = V + ((size_t)bh * NSEQ + kt * 64) * DD;
#pragma unroll
        for (int i = 0; i < 4; i++) {
            float4 vv = *(const float4*)(Vg + (size_t)vkey * DD + vdb + 4 * i);
            smf[OFF_V + (vdb + 4 * i + 0) * LDK + vkey] = vv.x;
            smf[OFF_V + (vdb + 4 * i + 1) * LDK + vkey] = vv.y;
            smf[OFF_V + (vdb + 4 * i + 2) * LDK + vkey] = vv.z;
            smf[OFF_V + (vdb + 4 * i + 3) * LDK + vkey] = vv.w;
        }
        __syncthreads();

        float s[8][4];
#pragma unroll
        for (int i = 0; i < 8; i++)
#pragma unroll
            for (int j = 0; j < 4; j++) s[i][j] = 0.f;
#pragma unroll
        for (int ks = 0; ks < 8; ks++) {
            uint32_t qa[4], kb[4][4];
            ldsm4(qa, qA + ks * 32);
#pragma unroll
            for (int p = 0; p < 4; p++)
                ldsm4(kb[p], kA + 4 * (p * 16 * LDK + ks * 8));
#pragma unroll
            for (int nt = 0; nt < 8; nt++)
                mma_tf32(s[nt], qa, &kb[nt >> 1][(nt & 1) * 2]);
        }

        float mx0 = -1e30f, mx1 = -1e30f;
#pragma unroll
        for (int nt = 0; nt < 8; nt++) {
            mx0 = fmaxf(mx0, fmaxf(s[nt][0], s[nt][1]));
            mx1 = fmaxf(mx1, fmaxf(s[nt][2], s[nt][3]));
        }
        mx0 = fmaxf(mx0, __shfl_xor_sync(0xffffffffu, mx0, 1));
        mx0 = fmaxf(mx0, __shfl_xor_sync(0xffffffffu, mx0, 2));
        mx1 = fmaxf(mx1, __shfl_xor_sync(0xffffffffu, mx1, 1));
        mx1 = fmaxf(mx1, __shfl_xor_sync(0xffffffffu, mx1, 2));
        float nm0 = fmaxf(m0r, mx0), nm1 = fmaxf(m1r, mx1);
        float al0 = __expf(m0r - nm0), al1 = __expf(m1r - nm1);
        float ts0 = 0.f, ts1 = 0.f;
        float* Pw = &smf[OFF_P + (wm * 16) * LDK];
#pragma unroll
        for (int nt = 0; nt < 8; nt++) {
            float p00 = __expf(s[nt][0] - nm0);
            float p01 = __expf(s[nt][1] - nm0);
            float p10 = __expf(s[nt][2] - nm1);
            float p11 = __expf(s[nt][3] - nm1);
            ts0 += p00 + p01; ts1 += p10 + p11;
            *(float2*)&Pw[g * LDK + nt * 8 + 2 * t] = make_float2(to_tf32(p00), to_tf32(p01));
            *(float2*)&Pw[(g + 8) * LDK + nt * 8 + 2 * t] = make_float2(to_tf32(p10), to_tf32(p11));
        }
        ts0 += __shfl_xor_sync(0xffffffffu, ts0, 1);
        ts0 += __shfl_xor_sync(0xffffffffu, ts0, 2);
        ts1 += __shfl_xor_sync(0xffffffffu, ts1, 1);
        ts1 += __shfl_xor_sync(0xffffffffu, ts1, 2);
        l0 = l0 * al0 + ts0;
        l1 = l1 * al1 + ts1;
        m0r = nm0; m1r = nm1;
#pragma unroll
        for (int nt = 0; nt < 8; nt++) {
            acc_o[nt][0] *= al0; acc_o[nt][1] *= al0;
            acc_o[nt][2] *= al1; acc_o[nt][3] *= al1;
        }
#pragma unroll
        for (int kk = 0; kk < 8; kk++) {
            uint32_t pa[4], vb[4][4];
            ldsm4(pa, pA + kk * 32);
#pragma unroll
            for (int p = 0; p < 4; p++)
                ldsm4(vb[p], vA + 4 * (p * 16 * LDK + kk * 8));
#pragma unroll
            for (int nt = 0; nt < 8; nt++)
                mma_tf32(acc_o[nt], pa, &vb[nt >> 1][(nt & 1) * 2]);
        }
        __syncthreads();
    }

    float inv0 = 1.0f / l0, inv1 = 1.0f / l1;
    int row0 = qbase + wm * 16 + g;
    float* Ob = O + ((size_t)b * NSEQ) * CDIM + h * DD;
#pragma unroll
    for (int nt = 0; nt < 8; nt++) {
        int col = nt * 8 + 2 * t;
        *(float2*)(Ob + (size_t)row0 * CDIM + col) =
            make_float2(to_tf32(acc_o[nt][0] * inv0), to_tf32(acc_o[nt][1] * inv0));
        *(float2*)(Ob + (size_t)(row0 + 8) * CDIM + col) =
            make_float2(to_tf32(acc_o[nt][2] * inv1), to_tf32(acc_o[nt][3] * inv1));
    }
}

// ---------------- host ----------------
extern "C" void kernel_launch(void* const* d_in, const int* in_sizes, int n_in,
                              void* d_out, int out_size) {
    const float* x      = (const float*)d_in[0];
    const float* ln1_g  = (const float*)d_in[1];
    const float* ln1_b  = (const float*)d_in[2];
    const float* qkv_w  = (const float*)d_in[3];
    const float* proj_w = (const float*)d_in[4];
    const float* proj_b = (const float*)d_in[5];
    const float* ln2_g  = (const float*)d_in[6];
    const float* ln2_b  = (const float*)d_in[7];
    const float* fc1_w  = (const float*)d_in[8];
    const float* fc1_b  = (const float*)d_in[9];
    const float* fc2_w  = (const float*)d_in[10];
    const float* fc2_b  = (const float*)d_in[11];
    float* out = (float*)d_out;

    float *h, *q, *k, *v, *o, *x1, *hid, *wqkv, *wproj, *wfc1, *wfc2;
    cudaGetSymbolAddress((void**)&h,    g_h);
    cudaGetSymbolAddress((void**)&q,    g_q);
    cudaGetSymbolAddress((void**)&k,    g_k);
    cudaGetSymbolAddress((void**)&v,    g_v);
    cudaGetSymbolAddress((void**)&o,    g_o);
    cudaGetSymbolAddress((void**)&x1,   g_x1);
    cudaGetSymbolAddress((void**)&hid,  g_hid);
    cudaGetSymbolAddress((void**)&wqkv, g_wqkv);
    cudaGetSymbolAddress((void**)&wproj, g_wproj);
    cudaGetSymbolAddress((void**)&wfc1, g_wfc1);
    cudaGetSymbolAddress((void**)&wfc2, g_wfc2);

    cudaFuncSetAttribute(attn_mma, cudaFuncAttributeMaxDynamicSharedMemorySize, ATT_SMEM);
    cudaFuncSetAttribute(gemm_cp<0>, cudaFuncAttributeMaxDynamicSharedMemorySize, GEMM_SMEM);
    cudaFuncSetAttribute(gemm_cp<1>, cudaFuncAttributeMaxDynamicSharedMemorySize, GEMM_SMEM);
    cudaFuncSetAttribute(gemm_cp<2>, cudaFuncAttributeMaxDynamicSharedMemorySize, GEMM_SMEM);

    // 0. pre-round weights to tf32
    int nmax = HIDD * CDIM;   // largest
    wcvt_kernel<<<dim3((nmax / 4 + 255) / 256, 4), 256>>>(
        qkv_w, wqkv, 3 * CDIM * CDIM, proj_w, wproj, CDIM * CDIM,
        fc1_w, wfc1, HIDD * CDIM, fc2_w, wfc2, CDIM * HIDD);
    // 1. LN1 (tf32-rounded h)
    ln_kernel<<<MROWS, 256>>>(x, ln1_g, ln1_b, h);
    // 2. QKV GEMM
    gemm_cp<0><<<dim3(3 * CDIM / 128, MROWS / 128), 256, GEMM_SMEM>>>(
        h, wqkv, nullptr, nullptr, nullptr, MROWS, 3 * CDIM, CDIM, q, k, v);
    // 3. attention
    attn_mma<<<dim3(NSEQ / 128, BB * HH), 256, ATT_SMEM>>>(q, k, v, o);
    // 4. proj + bias + residual(x)
    gemm_cp<1><<<dim3(CDIM / 128, MROWS / 128), 256, GEMM_SMEM>>>(
        o, wproj, proj_b, x, x1, MROWS, CDIM, CDIM, nullptr, nullptr, nullptr);
    // 5. LN2
    ln_kernel<<<MROWS, 256>>>(x1, ln2_g, ln2_b, h);
    // 6. FC1 + bias + GELU (tf32-rounded hid)
    gemm_cp<2><<<dim3(HIDD / 128, MROWS / 128), 256, GEMM_SMEM>>>(
        h, wfc1, fc1_b, nullptr, hid, MROWS, HIDD, CDIM, nullptr, nullptr, nullptr);
    // 7. FC2 + bias + residual(x1)
    gemm_cp<1><<<dim3(CDIM / 128, MROWS / 128), 256, GEMM_SMEM>>>(
        hid, wfc2, fc2_b, x1, out, MROWS, CDIM, HIDD, nullptr, nullptr, nullptr);
}

// round 7
// speedup vs baseline: 4.7580x; 1.0916x over previous
#include <cuda_runtime.h>
#include <cstdint>
#include <math.h>

#define BB 4
#define NSEQ 2048
#define CDIM 768
#define HH 12
#define DD 64
#define HIDD 3072
#define MROWS (BB * NSEQ)   // 8192

// ---------------- scratch ----------------
__device__ float g_h[MROWS * CDIM];
__device__ float g_q[MROWS * CDIM];
__device__ float g_k[MROWS * CDIM];
__device__ float g_v[MROWS * CDIM];     // [B,H,D,N] (d-major!)
__device__ float g_o[MROWS * CDIM];
__device__ float g_x1[MROWS * CDIM];
__device__ float g_hid[MROWS * HIDD];
// tf32-rounded weights
__device__ float g_wqkv[3 * CDIM * CDIM];
__device__ float g_wproj[CDIM * CDIM];
__device__ float g_wfc1[HIDD * CDIM];
__device__ float g_wfc2[CDIM * HIDD];

__device__ __forceinline__ float to_tf32(float x) {
    float y;
    asm("cvt.rna.tf32.f32 %0, %1;" : "=f"(y) : "f"(x));
    return y;
}
__device__ __forceinline__ uint32_t smem_u32(const void* p) {
    uint32_t a;
    asm("{ .reg .u64 t; cvta.to.shared.u64 t, %1; cvt.u32.u64 %0, t; }" : "=r"(a) : "l"(p));
    return a;
}
__device__ __forceinline__ void mma_tf32(float* d, const uint32_t* a, const uint32_t* b) {
    asm volatile(
        "mma.sync.aligned.m16n8k8.row.col.f32.tf32.tf32.f32 "
        "{%0,%1,%2,%3}, {%4,%5,%6,%7}, {%8,%9}, {%0,%1,%2,%3};"
        : "+f"(d[0]), "+f"(d[1]), "+f"(d[2]), "+f"(d[3])
        : "r"(a[0]), "r"(a[1]), "r"(a[2]), "r"(a[3]), "r"(b[0]), "r"(b[1]));
}
__device__ __forceinline__ void ldsm4(uint32_t* r, uint32_t addr) {
    asm volatile("ldmatrix.sync.aligned.m8n8.x4.shared.b16 {%0,%1,%2,%3}, [%4];"
                 : "=r"(r[0]), "=r"(r[1]), "=r"(r[2]), "=r"(r[3]) : "r"(addr));
}
__device__ __forceinline__ void cp16(uint32_t dst, const float* src) {
    asm volatile("cp.async.cg.shared.global [%0], [%1], 16;"
                 :: "r"(dst), "l"(__cvta_generic_to_global(src)));
}
#define CP_COMMIT() asm volatile("cp.async.commit_group;" ::: "memory")
#define CP_WAIT1()  asm volatile("cp.async.wait_group 1;" ::: "memory")

// ---------------- weight tf32 pre-round ----------------
__global__ __launch_bounds__(256) void wcvt_kernel(
    const float* s0, float* d0, int n0, const float* s1, float* d1, int n1,
    const float* s2, float* d2, int n2, const float* s3, float* d3, int n3) {
    const float* s; float* d; int n;
    switch (blockIdx.y) {
        case 0: s = s0; d = d0; n = n0; break;
        case 1: s = s1; d = d1; n = n1; break;
        case 2: s = s2; d = d2; n = n2; break;
        default: s = s3; d = d3; n = n3; break;
    }
    int i = (blockIdx.x * 256 + threadIdx.x) * 4;
    if (i < n) {
        float4 v = *(const float4*)(s + i);
        v.x = to_tf32(v.x); v.y = to_tf32(v.y); v.z = to_tf32(v.z); v.w = to_tf32(v.w);
        *(float4*)(d + i) = v;
    }
}

// ---------------- cp.async tensor-core GEMM: C = A[M,K] * W[Nn,K]^T ----------------
#define GS 3
#define STG_B 32768
#define GEMM_SMEM (GS * STG_B)

template <int EPI>
__global__ __launch_bounds__(256, 2) void gemm_cp(
    const float* __restrict__ A, const float* __restrict__ W,
    const float* __restrict__ bias, const float* __restrict__ res,
    float* __restrict__ C, int M, int Nn, int K,
    float* __restrict__ qout, float* __restrict__ kout, float* __restrict__ vout) {
    extern __shared__ char sm[];
    uint32_t sb = smem_u32(sm);
    int tid = threadIdx.x, lane = tid & 31, wid = tid >> 5;
    int warpM = wid & 1, warpN = wid >> 1;
    int g = lane >> 2, t = lane & 3;
    int rowBase = blockIdx.y * 128, colBase = blockIdx.x * 128;

    float acc[4][4][4];
#pragma unroll
    for (int i = 0; i < 4; i++)
#pragma unroll
        for (int j = 0; j < 4; j++)
#pragma unroll
            for (int e = 0; e < 4; e++) acc[i][j][e] = 0.f;

    const int r0 = tid >> 3;
    const int c16 = tid & 7;
    const uint32_t csw = (uint32_t)((c16 ^ (r0 & 7)) << 4);
    const float* Ab = A + (size_t)rowBase * K + c16 * 4;
    const float* Wb = W + (size_t)colBase * K + c16 * 4;

    const int r7 = lane & 7;
    const int hiA = lane >> 4;
    const int hiB = (lane >> 3) & 1;
    uint32_t rbA[4], rbB[2];
#pragma unroll
    for (int mt = 0; mt < 4; mt++)
        rbA[mt] = (uint32_t)((warpM * 64 + mt * 16 + (lane & 15)) * 128);
#pragma unroll
    for (int p = 0; p < 2; p++)
        rbB[p] = (uint32_t)((warpN * 32 + p * 16 + (lane & 7) + ((lane >> 4) << 3)) * 128) + 16384;

    const int nc = K >> 5;
#pragma unroll
    for (int s = 0; s < GS - 1; s++) {
        uint32_t sA = sb + s * STG_B;
        const float* Ac = Ab + s * 32;
        const float* Wc = Wb + s * 32;
#pragma unroll
        for (int i = 0; i < 4; i++) {
            int r = r0 + i * 32;
            cp16(sA + r * 128 + csw, Ac + (size_t)r * K);
            cp16(sA + 16384 + r * 128 + csw, Wc + (size_t)r * K);
        }
        CP_COMMIT();
    }

    for (int c = 0; c < nc; c++) {
        CP_WAIT1();
        __syncthreads();
        int nxt = c + GS - 1;
        if (nxt < nc) {
            uint32_t sA = sb + (nxt % GS) * STG_B;
            const float* Ac = Ab + nxt * 32;
            const float* Wc = Wb + nxt * 32;
#pragma unroll
            for (int i = 0; i < 4; i++) {
                int r = r0 + i * 32;
                cp16(sA + r * 128 + csw, Ac + (size_t)r * K);
                cp16(sA + 16384 + r * 128 + csw, Wc + (size_t)r * K);
            }
        }
        CP_COMMIT();
        uint32_t stg = sb + (c % GS) * STG_B;
#pragma unroll
        for (int ks = 0; ks < 4; ks++) {
            uint32_t colA = (uint32_t)((((2 * ks + hiA) ^ r7)) << 4);
            uint32_t colB = (uint32_t)((((2 * ks + hiB) ^ r7)) << 4);
            uint32_t af[4][4], bf[2][4];
#pragma unroll
            for (int mt = 0; mt < 4; mt++) ldsm4(af[mt], stg + rbA[mt] + colA);
#pragma unroll
            for (int p = 0; p < 2; p++) ldsm4(bf[p], stg + rbB[p] + colB);
#pragma unroll
            for (int mt = 0; mt < 4; mt++)
#pragma unroll
                for (int nt = 0; nt < 4; nt++)
                    mma_tf32(acc[mt][nt], af[mt], &bf[nt >> 1][(nt & 1) * 2]);
        }
    }

#pragma unroll
    for (int mt = 0; mt < 4; mt++) {
        int rlo = rowBase + warpM * 64 + mt * 16 + g;
#pragma unroll
        for (int nt = 0; nt < 4; nt++) {
            int colb = colBase + warpN * 32 + nt * 8 + t * 2;
#pragma unroll
            for (int half = 0; half < 2; half++) {
                int row = rlo + half * 8;
                float v0 = acc[mt][nt][half * 2 + 0];
                float v1 = acc[mt][nt][half * 2 + 1];
                if (EPI == 0) {
                    int which = colb / CDIM;
                    int rem = colb - which * CDIM;
                    int h = rem >> 6, d0 = rem & 63;
                    int bq = row >> 11, n = row & 2047;
                    if (which == 2) {
                        // V d-major: [B,H,D,N]
                        float* dst = vout + (((size_t)bq * HH + h) * DD + d0) * NSEQ + n;
                        dst[0] = to_tf32(v0);
                        dst[NSEQ] = to_tf32(v1);
                    } else {
                        float scale = (which == 0) ? 0.125f : 1.0f;
                        float* dst = (which == 0 ? qout : kout) +
                                     ((((size_t)bq * HH + h) * NSEQ + n) * DD + d0);
                        *(float2*)dst = make_float2(to_tf32(v0 * scale), to_tf32(v1 * scale));
                    }
                } else if (EPI == 1) {
                    float2 bv = *(const float2*)(bias + colb);
                    float2 rv = *(const float2*)(res + (size_t)row * Nn + colb);
                    *(float2*)(C + (size_t)row * Nn + colb) =
                        make_float2(v0 + bv.x + rv.x, v1 + bv.y + rv.y);
                } else {
                    float2 bv = *(const float2*)(bias + colb);
                    float u0 = v0 + bv.x, u1 = v1 + bv.y;
                    float2 o;
                    o.x = to_tf32(0.5f * u0 * (1.0f + erff(u0 * 0.70710678f)));
                    o.y = to_tf32(0.5f * u1 * (1.0f + erff(u1 * 0.70710678f)));
                    *(float2*)(C + (size_t)row * Nn + colb) = o;
                }
            }
        }
    }
}

// ---------------- LayerNorm (tf32-rounded output) ----------------
__global__ __launch_bounds__(256) void ln_kernel(const float* __restrict__ X,
                                                 const float* __restrict__ gam,
                                                 const float* __restrict__ bet,
                                                 float* __restrict__ out) {
    int row = blockIdx.x;
    const float* xr = X + (size_t)row * CDIM;
    float v[3];
    float s = 0.f, s2 = 0.f;
#pragma unroll
    for (int i = 0; i < 3; i++) {
        v[i] = xr[threadIdx.x + i * 256];
        s += v[i];
        s2 += v[i] * v[i];
    }
#pragma unroll
    for (int o = 16; o > 0; o >>= 1) {
        s  += __shfl_xor_sync(0xffffffffu, s, o);
        s2 += __shfl_xor_sync(0xffffffffu, s2, o);
    }
    __shared__ float ws[8], ws2[8];
    int wid = threadIdx.x >> 5, lane = threadIdx.x & 31;
    if (lane == 0) { ws[wid] = s; ws2[wid] = s2; }
    __syncthreads();
    if (wid == 0) {
        s  = (lane < 8) ? ws[lane] : 0.f;
        s2 = (lane < 8) ? ws2[lane] : 0.f;
#pragma unroll
        for (int o = 4; o > 0; o >>= 1) {
            s  += __shfl_xor_sync(0xffffffffu, s, o);
            s2 += __shfl_xor_sync(0xffffffffu, s2, o);
        }
        if (lane == 0) { ws[0] = s; ws2[0] = s2; }
    }
    __syncthreads();
    float mu   = ws[0] * (1.0f / CDIM);
    float var  = ws2[0] * (1.0f / CDIM) - mu * mu;
    float rstd = rsqrtf(var + 1e-5f);
#pragma unroll
    for (int i = 0; i < 3; i++) {
        int c = threadIdx.x + i * 256;
        out[(size_t)row * CDIM + c] = to_tf32((v[i] - mu) * rstd * gam[c] + bet[c]);
    }
}

// ---------------- Tensor-core flash attention (V pre-transposed d-major) ----------------
#define LDK 68
#define OFF_Q 0
#define OFF_K (128 * LDK)
#define OFF_V (OFF_K + 64 * LDK)
#define OFF_P (OFF_V + 64 * LDK)
#define ATT_SMEM ((OFF_P + 128 * LDK) * 4)

__global__ __launch_bounds__(256, 2) void attn_mma(const float* __restrict__ Q,
                                                   const float* __restrict__ K,
                                                   const float* __restrict__ V,
                                                   float* __restrict__ O) {
    extern __shared__ float smf[];
    uint32_t sbase = smem_u32(smf);
    int tid = threadIdx.x, lane = tid & 31, wm = tid >> 5;
    int g = lane >> 2, t = lane & 3;
    int bh = blockIdx.y;
    int b = bh / HH, h = bh - b * HH;
    int qbase = blockIdx.x * 128;

    {
        const float* Qg = Q + ((size_t)bh * NSEQ + qbase) * DD;
#pragma unroll
        for (int i = 0; i < 8; i++) {
            int idx = tid + i * 256;
            int r = idx >> 4, c4 = idx & 15;
            *(float4*)&smf[OFF_Q + r * LDK + c4 * 4] =
                *(const float4*)(Qg + (size_t)r * DD + c4 * 4);
        }
    }

    float acc_o[8][4];
#pragma unroll
    for (int i = 0; i < 8; i++)
#pragma unroll
        for (int j = 0; j < 4; j++) acc_o[i][j] = 0.f;
    float m0r = -1e30f, m1r = -1e30f, l0 = 0.f, l1 = 0.f;

    const uint32_t qA = sbase + 4 * (OFF_Q + (wm * 16 + (lane & 15)) * LDK + ((lane >> 4) << 2));
    const uint32_t kA = sbase + 4 * (OFF_K + ((lane & 7) + ((lane >> 4) << 3)) * LDK + (((lane >> 3) & 1) << 2));
    const uint32_t vA = sbase + 4 * (OFF_V + ((lane & 7) + ((lane >> 4) << 3)) * LDK + (((lane >> 3) & 1) << 2));
    const uint32_t pA = sbase + 4 * (OFF_P + (wm * 16 + (lane & 15)) * LDK + ((lane >> 4) << 2));

    const float* Kbase = K + (size_t)bh * NSEQ * DD;
    const float* Vbase = V + (size_t)bh * DD * NSEQ;   // d-major

    for (int kt = 0; kt < NSEQ / 64; kt++) {
        // stage K tile [64 keys][64 d]
#pragma unroll
        for (int i = 0; i < 4; i++) {
            int idx = tid + i * 256;
            int r = idx >> 4, c4 = idx & 15;
            *(float4*)&smf[OFF_K + r * LDK + c4 * 4] =
                *(const float4*)(Kbase + ((size_t)(kt * 64 + r)) * DD + c4 * 4);
        }
        // stage V tile [64 d][64 keys] — direct copy (already d-major)
#pragma unroll
        for (int i = 0; i < 4; i++) {
            int idx = tid + i * 256;
            int r = idx >> 4, c4 = idx & 15;
            *(float4*)&smf[OFF_V + r * LDK + c4 * 4] =
                *(const float4*)(Vbase + (size_t)r * NSEQ + kt * 64 + c4 * 4);
        }
        __syncthreads();

        float s[8][4];
#pragma unroll
        for (int i = 0; i < 8; i++)
#pragma unroll
            for (int j = 0; j < 4; j++) s[i][j] = 0.f;
#pragma unroll
        for (int ks = 0; ks < 8; ks++) {
            uint32_t qa[4], kb[4][4];
            ldsm4(qa, qA + ks * 32);
#pragma unroll
            for (int p = 0; p < 4; p++)
                ldsm4(kb[p], kA + 4 * (p * 16 * LDK + ks * 8));
#pragma unroll
            for (int nt = 0; nt < 8; nt++)
                mma_tf32(s[nt], qa, &kb[nt >> 1][(nt & 1) * 2]);
        }

        float mx0 = -1e30f, mx1 = -1e30f;
#pragma unroll
        for (int nt = 0; nt < 8; nt++) {
            mx0 = fmaxf(mx0, fmaxf(s[nt][0], s[nt][1]));
            mx1 = fmaxf(mx1, fmaxf(s[nt][2], s[nt][3]));
        }
        mx0 = fmaxf(mx0, __shfl_xor_sync(0xffffffffu, mx0, 1));
        mx0 = fmaxf(mx0, __shfl_xor_sync(0xffffffffu, mx0, 2));
        mx1 = fmaxf(mx1, __shfl_xor_sync(0xffffffffu, mx1, 1));
        mx1 = fmaxf(mx1, __shfl_xor_sync(0xffffffffu, mx1, 2));
        float nm0 = fmaxf(m0r, mx0), nm1 = fmaxf(m1r, mx1);
        float al0 = __expf(m0r - nm0), al1 = __expf(m1r - nm1);
        float ts0 = 0.f, ts1 = 0.f;
        float* Pw = &smf[OFF_P + (wm * 16) * LDK];
#pragma unroll
        for (int nt = 0; nt < 8; nt++) {
            float p00 = __expf(s[nt][0] - nm0);
            float p01 = __expf(s[nt][1] - nm0);
            float p10 = __expf(s[nt][2] - nm1);
            float p11 = __expf(s[nt][3] - nm1);
            ts0 += p00 + p01; ts1 += p10 + p11;
            *(float2*)&Pw[g * LDK + nt * 8 + 2 * t] = make_float2(to_tf32(p00), to_tf32(p01));
            *(float2*)&Pw[(g + 8) * LDK + nt * 8 + 2 * t] = make_float2(to_tf32(p10), to_tf32(p11));
        }
        ts0 += __shfl_xor_sync(0xffffffffu, ts0, 1);
        ts0 += __shfl_xor_sync(0xffffffffu, ts0, 2);
        ts1 += __shfl_xor_sync(0xffffffffu, ts1, 1);
        ts1 += __shfl_xor_sync(0xffffffffu, ts1, 2);
        l0 = l0 * al0 + ts0;
        l1 = l1 * al1 + ts1;
        m0r = nm0; m1r = nm1;
#pragma unroll
        for (int nt = 0; nt < 8; nt++) {
            acc_o[nt][0] *= al0; acc_o[nt][1] *= al0;
            acc_o[nt][2] *= al1; acc_o[nt][3] *= al1;
        }
#pragma unroll
        for (int kk = 0; kk < 8; kk++) {
            uint32_t pa[4], vb[4][4];
            ldsm4(pa, pA + kk * 32);
#pragma unroll
            for (int p = 0; p < 4; p++)
                ldsm4(vb[p], vA + 4 * (p * 16 * LDK + kk * 8));
#pragma unroll
            for (int nt = 0; nt < 8; nt++)
                mma_tf32(acc_o[nt], pa, &vb[nt >> 1][(nt & 1) * 2]);
        }
        __syncthreads();
    }

    float inv0 = 1.0f / l0, inv1 = 1.0f / l1;
    int row0 = qbase + wm * 16 + g;
    float* Ob = O + ((size_t)b * NSEQ) * CDIM + h * DD;
#pragma unroll
    for (int nt = 0; nt < 8; nt++) {
        int col = nt * 8 + 2 * t;
        *(float2*)(Ob + (size_t)row0 * CDIM + col) =
            make_float2(to_tf32(acc_o[nt][0] * inv0), to_tf32(acc_o[nt][1] * inv0));
        *(float2*)(Ob + (size_t)(row0 + 8) * CDIM + col) =
            make_float2(to_tf32(acc_o[nt][2] * inv1), to_tf32(acc_o[nt][3] * inv1));
    }
}

// ---------------- host ----------------
extern "C" void kernel_launch(void* const* d_in, const int* in_sizes, int n_in,
                              void* d_out, int out_size) {
    const float* x      = (const float*)d_in[0];
    const float* ln1_g  = (const float*)d_in[1];
    const float* ln1_b  = (const float*)d_in[2];
    const float* qkv_w  = (const float*)d_in[3];
    const float* proj_w = (const float*)d_in[4];
    const float* proj_b = (const float*)d_in[5];
    const float* ln2_g  = (const float*)d_in[6];
    const float* ln2_b  = (const float*)d_in[7];
    const float* fc1_w  = (const float*)d_in[8];
    const float* fc1_b  = (const float*)d_in[9];
    const float* fc2_w  = (const float*)d_in[10];
    const float* fc2_b  = (const float*)d_in[11];
    float* out = (float*)d_out;

    float *h, *q, *k, *v, *o, *x1, *hid, *wqkv, *wproj, *wfc1, *wfc2;
    cudaGetSymbolAddress((void**)&h,    g_h);
    cudaGetSymbolAddress((void**)&q,    g_q);
    cudaGetSymbolAddress((void**)&k,    g_k);
    cudaGetSymbolAddress((void**)&v,    g_v);
    cudaGetSymbolAddress((void**)&o,    g_o);
    cudaGetSymbolAddress((void**)&x1,   g_x1);
    cudaGetSymbolAddress((void**)&hid,  g_hid);
    cudaGetSymbolAddress((void**)&wqkv, g_wqkv);
    cudaGetSymbolAddress((void**)&wproj, g_wproj);
    cudaGetSymbolAddress((void**)&wfc1, g_wfc1);
    cudaGetSymbolAddress((void**)&wfc2, g_wfc2);

    cudaFuncSetAttribute(attn_mma, cudaFuncAttributeMaxDynamicSharedMemorySize, ATT_SMEM);
    cudaFuncSetAttribute(gemm_cp<0>, cudaFuncAttributeMaxDynamicSharedMemorySize, GEMM_SMEM);
    cudaFuncSetAttribute(gemm_cp<1>, cudaFuncAttributeMaxDynamicSharedMemorySize, GEMM_SMEM);
    cudaFuncSetAttribute(gemm_cp<2>, cudaFuncAttributeMaxDynamicSharedMemorySize, GEMM_SMEM);

    int nmax = HIDD * CDIM;
    wcvt_kernel<<<dim3((nmax / 4 + 255) / 256, 4), 256>>>(
        qkv_w, wqkv, 3 * CDIM * CDIM, proj_w, wproj, CDIM * CDIM,
        fc1_w, wfc1, HIDD * CDIM, fc2_w, wfc2, CDIM * HIDD);
    ln_kernel<<<MROWS, 256>>>(x, ln1_g, ln1_b, h);
    gemm_cp<0><<<dim3(3 * CDIM / 128, MROWS / 128), 256, GEMM_SMEM>>>(
        h, wqkv, nullptr, nullptr, nullptr, MROWS, 3 * CDIM, CDIM, q, k, v);
    attn_mma<<<dim3(NSEQ / 128, BB * HH), 256, ATT_SMEM>>>(q, k, v, o);
    gemm_cp<1><<<dim3(CDIM / 128, MROWS / 128), 256, GEMM_SMEM>>>(
        o, wproj, proj_b, x, x1, MROWS, CDIM, CDIM, nullptr, nullptr, nullptr);
    ln_kernel<<<MROWS, 256>>>(x1, ln2_g, ln2_b, h);
    gemm_cp<2><<<dim3(HIDD / 128, MROWS / 128), 256, GEMM_SMEM>>>(
        h, wfc1, fc1_b, nullptr, hid, MROWS, HIDD, CDIM, nullptr, nullptr, nullptr);
    gemm_cp<1><<<dim3(CDIM / 128, MROWS / 128), 256, GEMM_SMEM>>>(
        hid, wfc2, fc2_b, x1, out, MROWS, CDIM, HIDD, nullptr, nullptr, nullptr);
}